// round 13
// baseline (speedup 1.0000x reference)
#include <cuda_runtime.h>
#include <cuda_fp16.h>
#include <stdint.h>

// Problem constants (from reference): N_NODES=100000, N_EDGES=3200000
#define NMAX 100000
#define EMAX 3200000

// Scratch: device globals (no allocation allowed in kernel_launch)
__device__ __half2 g_vh[NMAX];          // vm*e^{i*va} packed as half2 (4 B/node)
__device__ float4 g_acc4[NMAX / 2];     // (p_imb,q_imb) pairs, float4-aliased

// ---------------------------------------------------------------------------
// K1: per-node masked select + trig precompute + init accumulators.
// 2 nodes per thread = 12 floats = 3 float4 loads per array; for even n all
// 9 loads are in-bounds and UNCONDITIONAL -> single front load batch, full
// MLP. Mask dtype (int32 vs byte-bool) resolved AFTER the loads, registers
// only. Odd-n tail handled by one scalar thread.
// cols: VM=0 VA=1 PG=2 QG=3 PD=4 QD=5
// ---------------------------------------------------------------------------
__global__ void __launch_bounds__(256)
node_prep_kernel(const float4* __restrict__ pred4,
                 const float4* __restrict__ target4,
                 const uint4* __restrict__ mask4,
                 float* __restrict__ out,
                 int n)
{
    // mask dtype probe (uniform across grid)
    bool okp = true;
    if (threadIdx.x < 16) {
        uint32_t v = ((const uint32_t*)mask4)[threadIdx.x];
        okp = (v <= 1u);
    }
    int mask_is32 = __syncthreads_and(okp);

    int j = blockIdx.x * blockDim.x + threadIdx.x;   // pair index
    if (j == 0) out[0] = 0.0f;
    int npairs = n >> 1;                             // full pairs
    float2* acc = (float2*)g_acc4;

    if (j < npairs) {
        int i0 = j * 2;

        // ---- front load batch: 9 unconditional 16B loads ------------------
        float4 p0 = __ldcs(&pred4[3 * j]);
        float4 p1 = __ldcs(&pred4[3 * j + 1]);
        float4 p2 = __ldcs(&pred4[3 * j + 2]);
        float4 t0 = __ldcs(&target4[3 * j]);
        float4 t1 = __ldcs(&target4[3 * j + 1]);
        float4 t2 = __ldcs(&target4[3 * j + 2]);
        uint4  w0 = __ldcs(&mask4[3 * j]);
        uint4  w1 = __ldcs(&mask4[3 * j + 1]);
        uint4  w2 = __ldcs(&mask4[3 * j + 2]);

        // ---- decode mask (registers only) ----------------------------------
        // int32 form: 12 words over w0..w2. byte form: first 12 bytes of
        // w0 (w0.x..w0.z hold 12 bytes). NOTE byte form packs 12 bools into
        // 3 words = w0 only... careful: 2 nodes * 6 bytes = 12 bytes = words
        // w0.x, w0.y, w0.z of the uint4 at byte offset 12j? No: byte layout
        // stride per pair is 12 bytes, not 48. Handle via separate path.
        int m[12];
        if (mask_is32) {
            m[0] = w0.x; m[1] = w0.y; m[2]  = w0.z; m[3]  = w0.w;
            m[4] = w1.x; m[5] = w1.y; m[6]  = w1.z; m[7]  = w1.w;
            m[8] = w2.x; m[9] = w2.y; m[10] = w2.z; m[11] = w2.w;
        } else {
            // byte-bool layout: 12 bytes per pair at byte offset 12*j
            const uint32_t* mmw = (const uint32_t*)mask4;
            uint32_t b0 = __ldcs(&mmw[3 * j]);
            uint32_t b1 = __ldcs(&mmw[3 * j + 1]);
            uint32_t b2 = __ldcs(&mmw[3 * j + 2]);
#pragma unroll
            for (int k = 0; k < 4; k++) {
                m[k]     = (b0 >> (8 * k)) & 0xFF;
                m[4 + k] = (b1 >> (8 * k)) & 0xFF;
                m[8 + k] = (b2 >> (8 * k)) & 0xFF;
            }
        }

        float pv[12] = {p0.x, p0.y, p0.z, p0.w, p1.x, p1.y,
                        p1.z, p1.w, p2.x, p2.y, p2.z, p2.w};
        float tv[12] = {t0.x, t0.y, t0.z, t0.w, t1.x, t1.y,
                        t1.z, t1.w, t2.x, t2.y, t2.z, t2.w};

        float v[12];
#pragma unroll
        for (int k = 0; k < 12; k++) v[k] = m[k] ? pv[k] : tv[k];

        {   // node i0: v[0..5]
            float s, c;
            sincosf(v[1], &s, &c);
            g_vh[i0] = __floats2half2_rn(v[0] * c, v[0] * s);
            acc[i0]  = make_float2(v[2] - v[4], v[3] - v[5]);
        }
        {   // node i0+1: v[6..11]
            float s, c;
            sincosf(v[7], &s, &c);
            g_vh[i0 + 1] = __floats2half2_rn(v[6] * c, v[6] * s);
            acc[i0 + 1]  = make_float2(v[8] - v[10], v[9] - v[11]);
        }
    } else if (j == npairs && (n & 1)) {
        // odd tail: scalar path for last node
        int i = n - 1;
        const float* p = (const float*)pred4 + (size_t)i * 6;
        const float* t = (const float*)target4 + (size_t)i * 6;
        float v[6];
#pragma unroll
        for (int k = 0; k < 6; k++) {
            int mk;
            if (mask_is32) mk = ((const int*)mask4)[(size_t)i * 6 + k];
            else           mk = ((const unsigned char*)mask4)[(size_t)i * 6 + k];
            v[k] = mk ? p[k] : t[k];
        }
        float s, c;
        sincosf(v[1], &s, &c);
        g_vh[i] = __floats2half2_rn(v[0] * c, v[0] * s);
        acc[i]  = make_float2(v[2] - v[4], v[3] - v[5]);
    }
}

// ---------------------------------------------------------------------------
// K2: 4 edges per thread (proven best). Stream loads via .cs (evict-first),
// all 8 half2 node gathers issued up-front for MLP, fp32 flow math,
// one red.global.add.v2.f32 per edge.
//   vv*cos(dva) = xs*xd + ys*yd ;  vv*sin(dva) = ys*xd - xs*yd
// Edge-index dtype probed per block (JAX demotes int64->int32 unless x64).
// ---------------------------------------------------------------------------
__global__ void edge_kernel(const void* __restrict__ ei_raw,
                            const float* __restrict__ ea,
                            int E, int n)
{
    bool ok = true;
    if (threadIdx.x < 16) {
        long long v = ((const long long*)ei_raw)[threadIdx.x];
        ok = (v >= 0 && v < (long long)n);
    }
    int is64 = __syncthreads_and(ok);

    int e = (blockIdx.x * blockDim.x + threadIdx.x) * 4;
    if (e >= E) return;

    float2* acc = (float2*)g_acc4;

    if (e + 3 < E) {
        int s[4], d[4];
        if (is64) {
            const long long* ei = (const long long*)ei_raw;
            longlong2 s01 = __ldcs((const longlong2*)(ei + e));
            longlong2 s23 = __ldcs((const longlong2*)(ei + e + 2));
            longlong2 d01 = __ldcs((const longlong2*)(ei + E + e));
            longlong2 d23 = __ldcs((const longlong2*)(ei + E + e + 2));
            s[0] = (int)s01.x; s[1] = (int)s01.y; s[2] = (int)s23.x; s[3] = (int)s23.y;
            d[0] = (int)d01.x; d[1] = (int)d01.y; d[2] = (int)d23.x; d[3] = (int)d23.y;
        } else {
            const int* ei = (const int*)ei_raw;
            int4 sv = __ldcs((const int4*)(ei + e));
            int4 dv = __ldcs((const int4*)(ei + E + e));
            s[0] = sv.x; s[1] = sv.y; s[2] = sv.z; s[3] = sv.w;
            d[0] = dv.x; d[1] = dv.y; d[2] = dv.z; d[3] = dv.w;
        }
        float4 gb01 = __ldcs((const float4*)(ea + (size_t)e * 2));
        float4 gb23 = __ldcs((const float4*)(ea + (size_t)e * 2 + 4));

        // issue all gathers first (independent -> high MLP)
        __half2 ush[4], udh[4];
#pragma unroll
        for (int k = 0; k < 4; k++) ush[k] = __ldg(&g_vh[s[k]]);
#pragma unroll
        for (int k = 0; k < 4; k++) udh[k] = __ldg(&g_vh[d[k]]);

        float gg[4] = {gb01.x, gb01.z, gb23.x, gb23.z};
        float bb[4] = {gb01.y, gb01.w, gb23.y, gb23.w};

#pragma unroll
        for (int k = 0; k < 4; k++) {
            float2 us = __half22float2(ush[k]);
            float2 ud = __half22float2(udh[k]);
            float vvc = us.x * ud.x + us.y * ud.y;
            float vvs = us.y * ud.x - us.x * ud.y;
            float pf = gg[k] * vvc + bb[k] * vvs;
            float qf = gg[k] * vvs - bb[k] * vvc;
            asm volatile("red.global.add.v2.f32 [%0], {%1, %2};"
                         :: "l"(&acc[s[k]]), "f"(-pf), "f"(-qf)
                         : "memory");
        }
    } else {
        for (int k = e; k < E; k++) {
            int s0, d0;
            if (is64) {
                const long long* ei = (const long long*)ei_raw;
                s0 = (int)ei[k];
                d0 = (int)ei[E + k];
            } else {
                const int* ei = (const int*)ei_raw;
                s0 = ei[k];
                d0 = ei[E + k];
            }
            float gg = ea[(size_t)k * 2];
            float bb = ea[(size_t)k * 2 + 1];
            float2 us = __half22float2(__ldg(&g_vh[s0]));
            float2 ud = __half22float2(__ldg(&g_vh[d0]));
            float vvc = us.x * ud.x + us.y * ud.y;
            float vvs = us.y * ud.x - us.x * ud.y;
            float pf = gg * vvc + bb * vvs;
            float qf = gg * vvs - bb * vvc;
            asm volatile("red.global.add.v2.f32 [%0], {%1, %2};"
                         :: "l"(&acc[s0]), "f"(-pf), "f"(-qf)
                         : "memory");
        }
    }
}

// ---------------------------------------------------------------------------
// K3: sum of squares, scaled by 1/n, atomically added into out[0]
// (zeroed by node_prep earlier in the stream). One float4 per thread.
// ---------------------------------------------------------------------------
__global__ void reduce_kernel(float* __restrict__ out, int n)
{
    int nq = n / 2;   // float4 count (pairs; odd tail handled below)
    int i = blockIdx.x * blockDim.x + threadIdx.x;

    float sum = 0.0f;
    if (i < nq) {
        float4 a = g_acc4[i];
        sum = a.x * a.x + a.y * a.y + a.z * a.z + a.w * a.w;
    }
    if (i == 0 && (n & 1)) {
        float2 a = ((const float2*)g_acc4)[n - 1];
        sum += a.x * a.x + a.y * a.y;
    }

#pragma unroll
    for (int off = 16; off > 0; off >>= 1)
        sum += __shfl_down_sync(0xFFFFFFFFu, sum, off);

    __shared__ float warp_sums[32];
    int lane = threadIdx.x & 31;
    int wid  = threadIdx.x >> 5;
    if (lane == 0) warp_sums[wid] = sum;
    __syncthreads();

    int nwarps = (blockDim.x + 31) >> 5;
    if (wid == 0) {
        float bsum = (lane < nwarps) ? warp_sums[lane] : 0.0f;
#pragma unroll
        for (int off = 16; off > 0; off >>= 1)
            bsum += __shfl_down_sync(0xFFFFFFFFu, bsum, off);
        if (lane == 0)
            atomicAdd(out, bsum / (float)n);
    }
}

extern "C" void kernel_launch(void* const* d_in, const int* in_sizes, int n_in,
                              void* d_out, int out_size)
{
    const float* pred       = (const float*)d_in[0];
    const float* target     = (const float*)d_in[1];
    const void*  edge_index = d_in[2];
    const float* edge_attr  = (const float*)d_in[3];
    const void*  mask       = d_in[4];

    int n = in_sizes[0] / 6;       // nodes
    int E = in_sizes[2] / 2;       // edges
    if (n > NMAX) n = NMAX;
    if (E > EMAX) E = EMAX;

    float* out = (float*)d_out;

    const int B = 256;
    int nunits = (n >> 1) + 1;     // pairs + possible odd tail unit
    node_prep_kernel<<<(nunits + B - 1) / B, B>>>((const float4*)pred,
                                                  (const float4*)target,
                                                  (const uint4*)mask, out, n);
    int equads = (E + 3) / 4;
    edge_kernel<<<(equads + B - 1) / B, B>>>(edge_index, edge_attr, E, n);
    int nq = n / 2;
    reduce_kernel<<<(nq + B - 1) / B, B>>>(out, n);
}